// round 6
// baseline (speedup 1.0000x reference)
#include <cuda_runtime.h>
#include <cstdint>

#define EPS 1e-06f
#define MAX_V 2000000

__device__ float4 g_x4[MAX_V];
__device__ double g_energy_acc;

// L2-only cached float4 gather (bypass L1 allocation).
__device__ __forceinline__ float4 ldcg4(const float4* p) {
    float4 v;
    asm volatile("ld.global.cg.v4.f32 {%0,%1,%2,%3}, [%4];"
                 : "=f"(v.x), "=f"(v.y), "=f"(v.z), "=f"(v.w) : "l"(p));
    return v;
}

// Repack x[V,3] -> g_x4[V] (w=0). Coalesced float4 loads into smem,
// conflict-free stride-3 reads, coalesced 16B stores. Also zeroes acc.
__global__ void __launch_bounds__(256)
repack_kernel(const float* __restrict__ x, int V)
{
    __shared__ float s[768];
    int tid  = threadIdx.x;
    int base = blockIdx.x * 256;

    if (blockIdx.x == 0 && tid == 0) g_energy_acc = 0.0;

    int nvert = min(256, V - base);
    int nflt  = nvert * 3;

    if (nvert == 256 && (((uintptr_t)(x + 3 * base)) & 15) == 0) {
        if (tid < 192) {
            float4 v = __ldg((const float4*)(x + 3 * base) + tid);
            s[4 * tid + 0] = v.x;
            s[4 * tid + 1] = v.y;
            s[4 * tid + 2] = v.z;
            s[4 * tid + 3] = v.w;
        }
    } else {
        for (int i = tid; i < nflt; i += 256)
            s[i] = __ldg(x + 3 * base + i);
    }
    __syncthreads();

    if (tid < nvert) {
        g_x4[base + tid] = make_float4(s[3 * tid], s[3 * tid + 1],
                                       s[3 * tid + 2], 0.0f);
    }
}

// 4 edges per thread; gathers via ld.global.cg (L2-only).
__global__ void __launch_bounds__(256, 6)
spring_energy_kernel(const int* __restrict__ indices,  // [E*2] int32
                     const float* __restrict__ l0,
                     const float* __restrict__ k,
                     long long E)
{
    long long t    = (long long)blockIdx.x * blockDim.x + threadIdx.x;
    long long base = 4 * t;

    float term = 0.0f;
    if (base + 3 < E) {
        int4 p = __ldg((const int4*)(indices + 2 * base));
        int4 q = __ldg((const int4*)(indices + 2 * base) + 1);
        float4 l04 = __ldg((const float4*)(l0 + base));
        float4 k4  = __ldg((const float4*)(k  + base));

        float4 a0 = ldcg4(&g_x4[p.x]);
        float4 b0 = ldcg4(&g_x4[p.y]);
        float4 a1 = ldcg4(&g_x4[p.z]);
        float4 b1 = ldcg4(&g_x4[p.w]);
        float4 a2 = ldcg4(&g_x4[q.x]);
        float4 b2 = ldcg4(&g_x4[q.y]);
        float4 a3 = ldcg4(&g_x4[q.z]);
        float4 b3 = ldcg4(&g_x4[q.w]);

        float d0, d1, d2, qq, l, dl;

        d0 = a0.x - b0.x; d1 = a0.y - b0.y; d2 = a0.z - b0.z;
        qq = fmaf(d0, d0, fmaf(d1, d1, d2 * d2));
        l  = sqrtf(qq + EPS); dl = l - l04.x;
        term = fmaf(0.5f * k4.x, dl * dl, term);

        d0 = a1.x - b1.x; d1 = a1.y - b1.y; d2 = a1.z - b1.z;
        qq = fmaf(d0, d0, fmaf(d1, d1, d2 * d2));
        l  = sqrtf(qq + EPS); dl = l - l04.y;
        term = fmaf(0.5f * k4.y, dl * dl, term);

        d0 = a2.x - b2.x; d1 = a2.y - b2.y; d2 = a2.z - b2.z;
        qq = fmaf(d0, d0, fmaf(d1, d1, d2 * d2));
        l  = sqrtf(qq + EPS); dl = l - l04.z;
        term = fmaf(0.5f * k4.z, dl * dl, term);

        d0 = a3.x - b3.x; d1 = a3.y - b3.y; d2 = a3.z - b3.z;
        qq = fmaf(d0, d0, fmaf(d1, d1, d2 * d2));
        l  = sqrtf(qq + EPS); dl = l - l04.w;
        term = fmaf(0.5f * k4.w, dl * dl, term);
    } else {
        for (long long e = base; e < E; e++) {
            int i = __ldg(indices + 2 * e);
            int j = __ldg(indices + 2 * e + 1);
            float4 a = ldcg4(&g_x4[i]);
            float4 b = ldcg4(&g_x4[j]);
            float d0 = a.x - b.x, d1 = a.y - b.y, d2 = a.z - b.z;
            float qq = fmaf(d0, d0, fmaf(d1, d1, d2 * d2));
            float l  = sqrtf(qq + EPS);
            float dl = l - __ldg(l0 + e);
            term = fmaf(0.5f * __ldg(k + e), dl * dl, term);
        }
    }

    #pragma unroll
    for (int off = 16; off > 0; off >>= 1)
        term += __shfl_down_sync(0xFFFFFFFFu, term, off);

    __shared__ float warp_sums[8];
    int lane = threadIdx.x & 31;
    int wid  = threadIdx.x >> 5;
    if (lane == 0) warp_sums[wid] = term;
    __syncthreads();

    if (wid == 0) {
        float v = (lane < 8) ? warp_sums[lane] : 0.0f;
        #pragma unroll
        for (int off = 4; off > 0; off >>= 1)
            v += __shfl_down_sync(0xFFFFFFFFu, v, off);
        if (lane == 0)
            atomicAdd(&g_energy_acc, (double)v);
    }
}

// Fallback (V > MAX_V): direct scalar gather from x.
__global__ void zero_acc_kernel() { g_energy_acc = 0.0; }

__global__ void __launch_bounds__(256)
spring_energy_fallback_kernel(const float* __restrict__ x,
                              const int2* __restrict__ indices,
                              const float* __restrict__ l0,
                              const float* __restrict__ k,
                              long long E)
{
    long long e = (long long)blockIdx.x * blockDim.x + threadIdx.x;
    float term = 0.0f;
    if (e < E) {
        int2 ij = __ldg(indices + e);
        const float* xi = x + 3LL * ij.x;
        const float* xj = x + 3LL * ij.y;
        float d0 = __ldg(xi + 0) - __ldg(xj + 0);
        float d1 = __ldg(xi + 1) - __ldg(xj + 1);
        float d2 = __ldg(xi + 2) - __ldg(xj + 2);
        float q = fmaf(d0, d0, fmaf(d1, d1, d2 * d2));
        float l = sqrtf(q + EPS);
        float dl = l - __ldg(l0 + e);
        term = 0.5f * __ldg(k + e) * dl * dl;
    }
    #pragma unroll
    for (int off = 16; off > 0; off >>= 1)
        term += __shfl_down_sync(0xFFFFFFFFu, term, off);
    __shared__ float warp_sums[8];
    int lane = threadIdx.x & 31;
    int wid  = threadIdx.x >> 5;
    if (lane == 0) warp_sums[wid] = term;
    __syncthreads();
    if (wid == 0) {
        float v = (lane < 8) ? warp_sums[lane] : 0.0f;
        #pragma unroll
        for (int off = 4; off > 0; off >>= 1)
            v += __shfl_down_sync(0xFFFFFFFFu, v, off);
        if (lane == 0)
            atomicAdd(&g_energy_acc, (double)v);
    }
}

__global__ void finalize_kernel(float* out) {
    out[0] = (float)g_energy_acc;
}

extern "C" void kernel_launch(void* const* d_in, const int* in_sizes, int n_in,
                              void* d_out, int out_size)
{
    const float* x       = (const float*)d_in[0];
    const int*   indices = (const int*)d_in[1];
    const float* l0      = (const float*)d_in[2];
    const float* k       = (const float*)d_in[3];
    float*       out     = (float*)d_out;

    int       V = in_sizes[0] / 3;
    long long E = (long long)in_sizes[2];

    const int threads = 256;

    if (V <= MAX_V) {
        int vblocks = (V + 255) / 256;
        repack_kernel<<<vblocks, threads>>>(x, V);
        long long eblocks = (E + 4LL * threads - 1) / (4LL * threads);
        spring_energy_kernel<<<(unsigned)eblocks, threads>>>(indices, l0, k, E);
    } else {
        zero_acc_kernel<<<1, 1>>>();
        long long eblocks = (E + threads - 1) / threads;
        spring_energy_fallback_kernel<<<(unsigned)eblocks, threads>>>(
            x, (const int2*)indices, l0, k, E);
    }

    finalize_kernel<<<1, 1>>>(out);
}

// round 7
// speedup vs baseline: 1.1054x; 1.1054x over previous
#include <cuda_runtime.h>
#include <cstdint>

#define EPS 1e-06f
#define MAX_V 2000000

// Fixed-point packing: sum in bits [0,48) at scale 2^16, block count at bit 48.
#define FP_SCALE   65536.0
#define COUNT_ONE  (1ULL << 48)
#define SUM_MASK   (COUNT_ONE - 1ULL)

__device__ float4 g_x4[MAX_V];
__device__ unsigned long long g_packed_acc;
__device__ double g_energy_acc;   // fallback path only

// Repack x[V,3] -> g_x4[V] (w=0); also resets the packed accumulator.
__global__ void __launch_bounds__(256)
repack_kernel(const float* __restrict__ x, int V)
{
    int v = blockIdx.x * blockDim.x + threadIdx.x;
    if (v == 0) {
        g_packed_acc = 0ULL;
        g_energy_acc = 0.0;
    }
    if (v < V) {
        float a = __ldg(x + 3 * v + 0);
        float b = __ldg(x + 3 * v + 1);
        float c = __ldg(x + 3 * v + 2);
        g_x4[v] = make_float4(a, b, c, 0.0f);
    }
}

// 4 edges per thread; single packed atomic per block; last block writes out.
__global__ void __launch_bounds__(256)
spring_energy_kernel(const int* __restrict__ indices,  // [E*2] int32
                     const float* __restrict__ l0,
                     const float* __restrict__ k,
                     long long E,
                     float* __restrict__ out)
{
    long long t    = (long long)blockIdx.x * blockDim.x + threadIdx.x;
    long long base = 4 * t;

    float term = 0.0f;
    if (base + 3 < E) {
        int4 p = __ldg((const int4*)(indices + 2 * base));
        int4 q = __ldg((const int4*)(indices + 2 * base) + 1);
        float4 l04 = __ldg((const float4*)(l0 + base));
        float4 k4  = __ldg((const float4*)(k  + base));

        float4 a0 = __ldg(&g_x4[p.x]);
        float4 b0 = __ldg(&g_x4[p.y]);
        float4 a1 = __ldg(&g_x4[p.z]);
        float4 b1 = __ldg(&g_x4[p.w]);
        float4 a2 = __ldg(&g_x4[q.x]);
        float4 b2 = __ldg(&g_x4[q.y]);
        float4 a3 = __ldg(&g_x4[q.z]);
        float4 b3 = __ldg(&g_x4[q.w]);

        float d0, d1, d2, qq, l, dl;

        d0 = a0.x - b0.x; d1 = a0.y - b0.y; d2 = a0.z - b0.z;
        qq = fmaf(d0, d0, fmaf(d1, d1, d2 * d2));
        l  = sqrtf(qq + EPS); dl = l - l04.x;
        term = fmaf(0.5f * k4.x, dl * dl, term);

        d0 = a1.x - b1.x; d1 = a1.y - b1.y; d2 = a1.z - b1.z;
        qq = fmaf(d0, d0, fmaf(d1, d1, d2 * d2));
        l  = sqrtf(qq + EPS); dl = l - l04.y;
        term = fmaf(0.5f * k4.y, dl * dl, term);

        d0 = a2.x - b2.x; d1 = a2.y - b2.y; d2 = a2.z - b2.z;
        qq = fmaf(d0, d0, fmaf(d1, d1, d2 * d2));
        l  = sqrtf(qq + EPS); dl = l - l04.z;
        term = fmaf(0.5f * k4.z, dl * dl, term);

        d0 = a3.x - b3.x; d1 = a3.y - b3.y; d2 = a3.z - b3.z;
        qq = fmaf(d0, d0, fmaf(d1, d1, d2 * d2));
        l  = sqrtf(qq + EPS); dl = l - l04.w;
        term = fmaf(0.5f * k4.w, dl * dl, term);
    } else {
        for (long long e = base; e < E; e++) {
            int i = __ldg(indices + 2 * e);
            int j = __ldg(indices + 2 * e + 1);
            float4 a = __ldg(&g_x4[i]);
            float4 b = __ldg(&g_x4[j]);
            float d0 = a.x - b.x, d1 = a.y - b.y, d2 = a.z - b.z;
            float qq = fmaf(d0, d0, fmaf(d1, d1, d2 * d2));
            float l  = sqrtf(qq + EPS);
            float dl = l - __ldg(l0 + e);
            term = fmaf(0.5f * __ldg(k + e), dl * dl, term);
        }
    }

    // Warp reduction
    #pragma unroll
    for (int off = 16; off > 0; off >>= 1)
        term += __shfl_down_sync(0xFFFFFFFFu, term, off);

    // Block reduction
    __shared__ float warp_sums[8];
    int lane = threadIdx.x & 31;
    int wid  = threadIdx.x >> 5;
    if (lane == 0) warp_sums[wid] = term;
    __syncthreads();

    if (wid == 0) {
        float v = (lane < 8) ? warp_sums[lane] : 0.0f;
        #pragma unroll
        for (int off = 4; off > 0; off >>= 1)
            v += __shfl_down_sync(0xFFFFFFFFu, v, off);
        if (lane == 0) {
            // ONE atomic: fixed-point block sum + count in high bits.
            // The returned old value makes "am I last?" race-free, no fence.
            unsigned long long add =
                (unsigned long long)((double)v * FP_SCALE + 0.5) + COUNT_ONE;
            unsigned long long old = atomicAdd(&g_packed_acc, add);
            unsigned long long now = old + add;
            if ((now >> 48) == (unsigned long long)gridDim.x) {
                out[0] = (float)((double)(now & SUM_MASK) / FP_SCALE);
            }
        }
    }
}

// ---- Fallback path (V > MAX_V): direct scalar gather from x ----
__global__ void zero_acc_kernel() { g_energy_acc = 0.0; }

__global__ void __launch_bounds__(256)
spring_energy_fallback_kernel(const float* __restrict__ x,
                              const int2* __restrict__ indices,
                              const float* __restrict__ l0,
                              const float* __restrict__ k,
                              long long E)
{
    long long e = (long long)blockIdx.x * blockDim.x + threadIdx.x;
    float term = 0.0f;
    if (e < E) {
        int2 ij = __ldg(indices + e);
        const float* xi = x + 3LL * ij.x;
        const float* xj = x + 3LL * ij.y;
        float d0 = __ldg(xi + 0) - __ldg(xj + 0);
        float d1 = __ldg(xi + 1) - __ldg(xj + 1);
        float d2 = __ldg(xi + 2) - __ldg(xj + 2);
        float q = fmaf(d0, d0, fmaf(d1, d1, d2 * d2));
        float l = sqrtf(q + EPS);
        float dl = l - __ldg(l0 + e);
        term = 0.5f * __ldg(k + e) * dl * dl;
    }
    #pragma unroll
    for (int off = 16; off > 0; off >>= 1)
        term += __shfl_down_sync(0xFFFFFFFFu, term, off);
    __shared__ float warp_sums[8];
    int lane = threadIdx.x & 31;
    int wid  = threadIdx.x >> 5;
    if (lane == 0) warp_sums[wid] = term;
    __syncthreads();
    if (wid == 0) {
        float v = (lane < 8) ? warp_sums[lane] : 0.0f;
        #pragma unroll
        for (int off = 4; off > 0; off >>= 1)
            v += __shfl_down_sync(0xFFFFFFFFu, v, off);
        if (lane == 0)
            atomicAdd(&g_energy_acc, (double)v);
    }
}

__global__ void finalize_kernel(float* out) {
    out[0] = (float)g_energy_acc;
}

extern "C" void kernel_launch(void* const* d_in, const int* in_sizes, int n_in,
                              void* d_out, int out_size)
{
    const float* x       = (const float*)d_in[0];
    const int*   indices = (const int*)d_in[1];
    const float* l0      = (const float*)d_in[2];
    const float* k       = (const float*)d_in[3];
    float*       out     = (float*)d_out;

    int       V = in_sizes[0] / 3;
    long long E = (long long)in_sizes[2];

    const int threads = 256;

    if (V <= MAX_V) {
        int vblocks = (V + threads - 1) / threads;
        repack_kernel<<<vblocks, threads>>>(x, V);
        long long eblocks = (E + 4LL * threads - 1) / (4LL * threads);
        spring_energy_kernel<<<(unsigned)eblocks, threads>>>(indices, l0, k, E, out);
    } else {
        zero_acc_kernel<<<1, 1>>>();
        long long eblocks = (E + threads - 1) / threads;
        spring_energy_fallback_kernel<<<(unsigned)eblocks, threads>>>(
            x, (const int2*)indices, l0, k, E);
        finalize_kernel<<<1, 1>>>(out);
    }
}